// round 1
// baseline (speedup 1.0000x reference)
#include <cuda_runtime.h>

#define BB 32
#define CC 448
#define HWI 32
#define PIN 1024       // 32*32
#define HWF 64
#define NPOS 4096
#define DP 100
#define DPAD 104
#define OHW 256

// ---- scratch (static device globals; no allocation) ----
__device__ float g_WT[CC * DPAD];          // [c][d], zero-padded d>=100
__device__ float g_meanT[NPOS * DP];       // [n][c]
__device__ float g_proj[(size_t)BB * PIN * DP];  // [b][p][d]  (13.1 MB)
__device__ float g_dist[(size_t)BB * NPOS];      // [b][n]

// ---------------------------------------------------------------------------
// Prep: transpose proj_w [100][448] -> WT[448][104] (pad), mean [100][4096] -> meanT[4096][100]
// ---------------------------------------------------------------------------
__global__ void prep_kernel(const float* __restrict__ W,
                            const float* __restrict__ mean) {
    int i = blockIdx.x * blockDim.x + threadIdx.x;
    const int NWT = CC * DPAD;
    if (i < NWT) {
        int c = i / DPAD, d = i - c * DPAD;
        g_WT[i] = (d < DP) ? W[d * CC + c] : 0.f;
    } else {
        int j = i - NWT;
        if (j < NPOS * DP) {
            int n = j / DP, c = j - n * DP;
            g_meanT[j] = mean[c * NPOS + n];
        }
    }
}

// ---------------------------------------------------------------------------
// Projection at 32x32: proj[b][p][d] = sum_c X[b][c][p] * W[d][c] + bias[d]
// Tile: 64 p x 104 d per block, thread = 8p x 8d register tile. 104 threads.
// ---------------------------------------------------------------------------
__global__ __launch_bounds__(104) void proj_kernel(const float* __restrict__ X,
                                                   const float* __restrict__ bias) {
    __shared__ float Xs[32][64];     // [c][p]
    __shared__ float Ws[32][DPAD];   // [c][d]
    const int tid = threadIdx.x;
    const int ptile = blockIdx.x;    // 0..15
    const int b = blockIdx.y;        // 0..31
    const int pg = tid & 7;          // p base = pg*8
    const int dg = tid >> 3;         // 0..12, d base = dg*8

    float4 a0[8], a1[8];
#pragma unroll
    for (int k = 0; k < 8; k++) {
        a0[k] = make_float4(0.f, 0.f, 0.f, 0.f);
        a1[k] = make_float4(0.f, 0.f, 0.f, 0.f);
    }

    const float* Xb = X + ((size_t)b * CC) * PIN + ptile * 64;

    for (int c0 = 0; c0 < CC; c0 += 32) {
        for (int i = tid; i < 32 * 64; i += 104) {
            int c = i >> 6, p = i & 63;
            Xs[c][p] = Xb[(size_t)(c0 + c) * PIN + p];
        }
#pragma unroll
        for (int k = 0; k < 32; k++)
            Ws[k][tid] = g_WT[(c0 + k) * DPAD + tid];
        __syncthreads();

#pragma unroll 4
        for (int c = 0; c < 32; c++) {
            float4 x0 = *(const float4*)&Xs[c][pg * 8];
            float4 x1 = *(const float4*)&Xs[c][pg * 8 + 4];
            float4 w0 = *(const float4*)&Ws[c][dg * 8];
            float4 w1 = *(const float4*)&Ws[c][dg * 8 + 4];
            float xv[8] = {x0.x, x0.y, x0.z, x0.w, x1.x, x1.y, x1.z, x1.w};
#pragma unroll
            for (int k = 0; k < 8; k++) {
                a0[k].x += xv[k] * w0.x; a0[k].y += xv[k] * w0.y;
                a0[k].z += xv[k] * w0.z; a0[k].w += xv[k] * w0.w;
                a1[k].x += xv[k] * w1.x; a1[k].y += xv[k] * w1.y;
                a1[k].z += xv[k] * w1.z; a1[k].w += xv[k] * w1.w;
            }
        }
        __syncthreads();
    }

    const int d0 = dg * 8;
    float4 bi0 = *(const float4*)&bias[d0];
    float4 bi1 = make_float4(0.f, 0.f, 0.f, 0.f);
    if (dg < 12) bi1 = *(const float4*)&bias[d0 + 4];
    const int pbase = ptile * 64 + pg * 8;
#pragma unroll
    for (int k = 0; k < 8; k++) {
        float* o = g_proj + ((size_t)b * PIN + pbase + k) * DP + d0;
        float4 r0 = make_float4(a0[k].x + bi0.x, a0[k].y + bi0.y,
                                a0[k].z + bi0.z, a0[k].w + bi0.w);
        *(float4*)o = r0;
        if (dg < 12) {
            float4 r1 = make_float4(a1[k].x + bi1.x, a1[k].y + bi1.y,
                                    a1[k].z + bi1.z, a1[k].w + bi1.w);
            *(float4*)(o + 4) = r1;
        }
    }
}

// ---------------------------------------------------------------------------
// Fused 2x bilinear upsample + mean-subtract + Mahalanobis quadratic form.
// One block per position n (4096 blocks). 128 threads.
// Phase 1: build diff^T in smem: DmT[c][b] for c<100, b<32 (via bilinear taps).
// Phase 2: thread (bg= (t&3)*8, d0=(t>>2)*4), t<100: v[b][d] = sum_c DmT[c][b]*IC[c][d],
//          then dist[b] += sum_d v[b][d]*DmT[d][b].
// ---------------------------------------------------------------------------
__global__ __launch_bounds__(128) void maha_kernel(const float* __restrict__ ic) {
    __shared__ float DmT[DP][36];   // pad to 36 floats (16B-aligned rows, fewer conflicts)
    __shared__ float dists[BB];
    const int n = blockIdx.x;
    const int tid = threadIdx.x;

    // bilinear source taps for this output position (half-pixel centers, clamped)
    const int yo = n >> 6, xo = n & 63;
    float yin = (yo + 0.5f) * 0.5f - 0.5f;
    float xin = (xo + 0.5f) * 0.5f - 0.5f;
    int y0 = (int)floorf(yin), x0 = (int)floorf(xin);
    float fy = yin - (float)y0, fx = xin - (float)x0;
    int y0c = max(y0, 0), y1c = min(y0 + 1, HWI - 1);
    int x0c = max(x0, 0), x1c = min(x0 + 1, HWI - 1);
    float w00 = (1.f - fy) * (1.f - fx), w01 = (1.f - fy) * fx;
    float w10 = fy * (1.f - fx),         w11 = fy * fx;
    int p00 = y0c * HWI + x0c, p01 = y0c * HWI + x1c;
    int p10 = y1c * HWI + x0c, p11 = y1c * HWI + x1c;

    const float* mt = g_meanT + (size_t)n * DP;
    for (int idx = tid; idx < BB * DP; idx += 128) {
        int b = idx / DP;
        int c = idx - b * DP;
        const float* P = g_proj + (size_t)b * PIN * DP;
        float v = w00 * P[p00 * DP + c] + w01 * P[p01 * DP + c]
                + w10 * P[p10 * DP + c] + w11 * P[p11 * DP + c] - mt[c];
        DmT[c][b] = v;
    }
    if (tid < BB) dists[tid] = 0.f;
    __syncthreads();

    if (tid < 100) {
        const int bg = (tid & 3) * 8;        // batch base (0,8,16,24)
        const int d0 = (tid >> 2) * 4;       // d base (0..96)
        const float* icn = ic + (size_t)n * (DP * DP) + d0;

        float4 v[8];
#pragma unroll
        for (int j = 0; j < 8; j++) v[j] = make_float4(0.f, 0.f, 0.f, 0.f);

#pragma unroll 4
        for (int c = 0; c < DP; c++) {
            float4 icv = __ldg(reinterpret_cast<const float4*>(icn + c * DP));
            float dm[8];
            *(float4*)&dm[0] = *(const float4*)&DmT[c][bg];
            *(float4*)&dm[4] = *(const float4*)&DmT[c][bg + 4];
#pragma unroll
            for (int j = 0; j < 8; j++) {
                v[j].x += dm[j] * icv.x;
                v[j].y += dm[j] * icv.y;
                v[j].z += dm[j] * icv.z;
                v[j].w += dm[j] * icv.w;
            }
        }
#pragma unroll
        for (int j = 0; j < 8; j++) {
            int b = bg + j;
            float s = v[j].x * DmT[d0][b] + v[j].y * DmT[d0 + 1][b]
                    + v[j].z * DmT[d0 + 2][b] + v[j].w * DmT[d0 + 3][b];
            atomicAdd(&dists[b], s);
        }
    }
    __syncthreads();
    if (tid < BB) g_dist[(size_t)tid * NPOS + n] = dists[tid];
}

// ---------------------------------------------------------------------------
// Normalize + 4x bilinear upsample 64x64 -> 256x256
// ---------------------------------------------------------------------------
__global__ void upsample_kernel(const float* __restrict__ nmin_p,
                                const float* __restrict__ nmax_p,
                                float* __restrict__ out) {
    const int b = blockIdx.y;
    const int i = blockIdx.x * blockDim.x + threadIdx.x;  // 0..65535
    const int yo = i >> 8, xo = i & 255;
    float yin = (yo + 0.5f) * 0.25f - 0.5f;
    float xin = (xo + 0.5f) * 0.25f - 0.5f;
    int y0 = (int)floorf(yin), x0 = (int)floorf(xin);
    float fy = yin - (float)y0, fx = xin - (float)x0;
    int y0c = max(y0, 0), y1c = min(y0 + 1, HWF - 1);
    int x0c = max(x0, 0), x1c = min(x0 + 1, HWF - 1);
    const float* dn = g_dist + (size_t)b * NPOS;
    float v00 = dn[y0c * HWF + x0c], v01 = dn[y0c * HWF + x1c];
    float v10 = dn[y1c * HWF + x0c], v11 = dn[y1c * HWF + x1c];
    float v = (1.f - fy) * ((1.f - fx) * v00 + fx * v01)
            + fy * ((1.f - fx) * v10 + fx * v11);
    float nmin = *nmin_p, nmax = *nmax_p;
    out[(size_t)b * (OHW * OHW) + i] = (v - nmin) / (nmax - nmin + 1e-8f);
}

// ---------------------------------------------------------------------------
extern "C" void kernel_launch(void* const* d_in, const int* in_sizes, int n_in,
                              void* d_out, int out_size) {
    (void)in_sizes; (void)n_in; (void)out_size;
    const float* combined = (const float*)d_in[0];
    const float* proj_w   = (const float*)d_in[1];
    const float* proj_b   = (const float*)d_in[2];
    const float* mean     = (const float*)d_in[3];
    const float* inv_cov  = (const float*)d_in[4];
    const float* nmin     = (const float*)d_in[5];
    const float* nmax     = (const float*)d_in[6];
    float* out = (float*)d_out;

    const int prep_total = CC * DPAD + NPOS * DP;
    prep_kernel<<<(prep_total + 255) / 256, 256>>>(proj_w, mean);
    proj_kernel<<<dim3(16, BB), 104>>>(combined, proj_b);
    maha_kernel<<<NPOS, 128>>>(inv_cov);
    upsample_kernel<<<dim3(OHW * OHW / 256, BB), 256>>>(nmin, nmax, out);
}

// round 2
// speedup vs baseline: 1.0805x; 1.0805x over previous
#include <cuda_runtime.h>

#define BB 32
#define CC 448
#define HWI 32
#define PIN 1024       // 32*32
#define HWF 64
#define NPOS 4096
#define DP 100
#define DPAD 104
#define OHW 256

// ---- packed f32x2 helpers (sm_103a) ----
__device__ __forceinline__ unsigned long long pack2(float lo, float hi) {
    unsigned long long r;
    asm("mov.b64 %0, {%1, %2};" : "=l"(r) : "f"(lo), "f"(hi));
    return r;
}
__device__ __forceinline__ float2 unpack2(unsigned long long v) {
    float lo, hi;
    asm("mov.b64 {%0, %1}, %2;" : "=f"(lo), "=f"(hi) : "l"(v));
    return make_float2(lo, hi);
}
__device__ __forceinline__ unsigned long long fma2(unsigned long long a,
                                                   unsigned long long b,
                                                   unsigned long long c) {
    unsigned long long d;
    asm("fma.rn.f32x2 %0, %1, %2, %3;" : "=l"(d) : "l"(a), "l"(b), "l"(c));
    return d;
}

// ---- scratch (static device globals; no allocation) ----
__device__ float g_WT[CC * DPAD];          // [c][d], zero-padded d>=100
__device__ float g_meanT[NPOS * DP];       // [n][c]
__device__ float g_proj[(size_t)BB * PIN * DP];  // [b][p][d]  (13.1 MB)
__device__ float g_dist[(size_t)BB * NPOS];      // [b][n]

// ---------------------------------------------------------------------------
// Prep: transpose proj_w [100][448] -> WT[448][104] (pad), mean [100][4096] -> meanT[4096][100]
// ---------------------------------------------------------------------------
__global__ void prep_kernel(const float* __restrict__ W,
                            const float* __restrict__ mean) {
    int i = blockIdx.x * blockDim.x + threadIdx.x;
    const int NWT = CC * DPAD;
    if (i < NWT) {
        int c = i / DPAD, d = i - c * DPAD;
        g_WT[i] = (d < DP) ? W[d * CC + c] : 0.f;
    } else {
        int j = i - NWT;
        if (j < NPOS * DP) {
            int n = j / DP, c = j - n * DP;
            g_meanT[j] = mean[c * NPOS + n];
        }
    }
}

// ---------------------------------------------------------------------------
// Projection at 32x32: proj[b][p][d] = sum_c X[b][c][p] * W[d][c] + bias[d]
// Tile: 64 p x 104 d per block, thread = 8p x 8d register tile (f32x2 pairs
// along d). 104 threads.
// ---------------------------------------------------------------------------
__global__ __launch_bounds__(104) void proj_kernel(const float* __restrict__ X,
                                                   const float* __restrict__ bias) {
    __shared__ float Xs[32][64];     // [c][p]
    __shared__ float Ws[32][DPAD];   // [c][d]  row stride 416B (16B-aligned)
    const int tid = threadIdx.x;
    const int ptile = blockIdx.x;    // 0..15
    const int b = blockIdx.y;        // 0..31
    const int pg = tid & 7;          // p base = pg*8
    const int dg = tid >> 3;         // 0..12, d base = dg*8
    const int d0 = dg * 8;

    unsigned long long acc[8][4];    // [p][d-pair], pair = (d0+2q, d0+2q+1)
#pragma unroll
    for (int k = 0; k < 8; k++)
#pragma unroll
        for (int q = 0; q < 4; q++) acc[k][q] = 0ull;

    const float* Xb = X + ((size_t)b * CC) * PIN + ptile * 64;

    for (int c0 = 0; c0 < CC; c0 += 32) {
        for (int i = tid; i < 32 * 64; i += 104) {
            int c = i >> 6, p = i & 63;
            Xs[c][p] = Xb[(size_t)(c0 + c) * PIN + p];
        }
#pragma unroll
        for (int k = 0; k < 32; k++)
            Ws[k][tid] = g_WT[(c0 + k) * DPAD + tid];
        __syncthreads();

#pragma unroll 4
        for (int c = 0; c < 32; c++) {
            float4 x0 = *(const float4*)&Xs[c][pg * 8];
            float4 x1 = *(const float4*)&Xs[c][pg * 8 + 4];
            ulonglong2 wa = *(const ulonglong2*)&Ws[c][d0];
            ulonglong2 wb = *(const ulonglong2*)&Ws[c][d0 + 4];
            unsigned long long wp[4] = {wa.x, wa.y, wb.x, wb.y};
            float xv[8] = {x0.x, x0.y, x0.z, x0.w, x1.x, x1.y, x1.z, x1.w};
            unsigned long long xd[8];
#pragma unroll
            for (int k = 0; k < 8; k++) xd[k] = pack2(xv[k], xv[k]);
#pragma unroll
            for (int k = 0; k < 8; k++)
#pragma unroll
                for (int q = 0; q < 4; q++)
                    acc[k][q] = fma2(xd[k], wp[q], acc[k][q]);
        }
        __syncthreads();
    }

    float4 bi0 = *(const float4*)&bias[d0];
    float4 bi1 = make_float4(0.f, 0.f, 0.f, 0.f);
    if (dg < 12) bi1 = *(const float4*)&bias[d0 + 4];
    const int pbase = ptile * 64 + pg * 8;
#pragma unroll
    for (int k = 0; k < 8; k++) {
        float* o = g_proj + ((size_t)b * PIN + pbase + k) * DP + d0;
        float2 u0 = unpack2(acc[k][0]);
        float2 u1 = unpack2(acc[k][1]);
        *(float4*)o = make_float4(u0.x + bi0.x, u0.y + bi0.y,
                                  u1.x + bi0.z, u1.y + bi0.w);
        if (dg < 12) {
            float2 u2 = unpack2(acc[k][2]);
            float2 u3 = unpack2(acc[k][3]);
            *(float4*)(o + 4) = make_float4(u2.x + bi1.x, u2.y + bi1.y,
                                            u3.x + bi1.z, u3.y + bi1.w);
        }
    }
}

// ---------------------------------------------------------------------------
// Fused 2x bilinear upsample + mean-subtract + Mahalanobis quadratic form.
// One block per position n (4096 blocks). 128 threads.
// Phase 1: build diff^T in smem: DmT[c][b] (b-minor, row padded to 40).
// Phase 2: thread (bg=(t&3)*8, d0=(t>>2)*4), t<100:
//   v[bpair][d] += DmT[c][bpair] * IC[c][d]   (f32x2 pairs along b)
//   then dist[b] += sum_d v[b][d]*DmT[d][b].
// ---------------------------------------------------------------------------
__global__ __launch_bounds__(128) void maha_kernel(const float* __restrict__ ic) {
    __shared__ float DmT[DP][40];   // row stride 160B (16B-aligned)
    __shared__ float dists[BB];
    const int n = blockIdx.x;
    const int tid = threadIdx.x;

    // bilinear source taps (half-pixel centers, clamped)
    const int yo = n >> 6, xo = n & 63;
    float yin = (yo + 0.5f) * 0.5f - 0.5f;
    float xin = (xo + 0.5f) * 0.5f - 0.5f;
    int y0 = (int)floorf(yin), x0 = (int)floorf(xin);
    float fy = yin - (float)y0, fx = xin - (float)x0;
    int y0c = max(y0, 0), y1c = min(y0 + 1, HWI - 1);
    int x0c = max(x0, 0), x1c = min(x0 + 1, HWI - 1);
    float w00 = (1.f - fy) * (1.f - fx), w01 = (1.f - fy) * fx;
    float w10 = fy * (1.f - fx),         w11 = fy * fx;
    int p00 = y0c * HWI + x0c, p01 = y0c * HWI + x1c;
    int p10 = y1c * HWI + x0c, p11 = y1c * HWI + x1c;

    const float* mt = g_meanT + (size_t)n * DP;
    for (int idx = tid; idx < BB * DP; idx += 128) {
        int b = idx / DP;
        int c = idx - b * DP;
        const float* P = g_proj + (size_t)b * PIN * DP;
        float v = w00 * P[p00 * DP + c] + w01 * P[p01 * DP + c]
                + w10 * P[p10 * DP + c] + w11 * P[p11 * DP + c] - mt[c];
        DmT[c][b] = v;
    }
    if (tid < BB) dists[tid] = 0.f;
    __syncthreads();

    if (tid < 100) {
        const int bg = (tid & 3) * 8;        // batch base (0,8,16,24)
        const int d0 = (tid >> 2) * 4;       // d base (0..96)
        const float* icn = ic + (size_t)n * (DP * DP) + d0;

        unsigned long long acc[4][4];        // [b-pair j][d-component q]
#pragma unroll
        for (int j = 0; j < 4; j++)
#pragma unroll
            for (int q = 0; q < 4; q++) acc[j][q] = 0ull;

#pragma unroll 4
        for (int c = 0; c < DP; c++) {
            float4 icv = __ldg(reinterpret_cast<const float4*>(icn + c * DP));
            unsigned long long icd[4];
            icd[0] = pack2(icv.x, icv.x);
            icd[1] = pack2(icv.y, icv.y);
            icd[2] = pack2(icv.z, icv.z);
            icd[3] = pack2(icv.w, icv.w);
            ulonglong2 da = *(const ulonglong2*)&DmT[c][bg];
            ulonglong2 db = *(const ulonglong2*)&DmT[c][bg + 4];
            unsigned long long dm[4] = {da.x, da.y, db.x, db.y};
#pragma unroll
            for (int j = 0; j < 4; j++)
#pragma unroll
                for (int q = 0; q < 4; q++)
                    acc[j][q] = fma2(dm[j], icd[q], acc[j][q]);
        }
#pragma unroll
        for (int j = 0; j < 4; j++) {
            unsigned long long s2 = 0ull;
#pragma unroll
            for (int q = 0; q < 4; q++) {
                unsigned long long dp =
                    *(const unsigned long long*)&DmT[d0 + q][bg + 2 * j];
                s2 = fma2(acc[j][q], dp, s2);
            }
            float2 s = unpack2(s2);
            atomicAdd(&dists[bg + 2 * j], s.x);
            atomicAdd(&dists[bg + 2 * j + 1], s.y);
        }
    }
    __syncthreads();
    if (tid < BB) g_dist[(size_t)tid * NPOS + n] = dists[tid];
}

// ---------------------------------------------------------------------------
// Normalize + 4x bilinear upsample 64x64 -> 256x256 (4 outputs/thread)
// ---------------------------------------------------------------------------
__global__ void upsample_kernel(const float* __restrict__ nmin_p,
                                const float* __restrict__ nmax_p,
                                float* __restrict__ out) {
    const int b = blockIdx.y;
    const int i = blockIdx.x * blockDim.x + threadIdx.x;  // 0..16383
    const int yo = i >> 6;              // 0..255
    const int xb = (i & 63) * 4;        // x base, 4 outputs

    float yin = (yo + 0.5f) * 0.25f - 0.5f;
    int y0 = (int)floorf(yin);
    float fy = yin - (float)y0;
    int y0c = max(y0, 0), y1c = min(y0 + 1, HWF - 1);

    const float* dn = g_dist + (size_t)b * NPOS;
    const float* r0 = dn + y0c * HWF;
    const float* r1 = dn + y1c * HWF;
    float nmin = *nmin_p, nmax = *nmax_p;
    float inv = 1.f / (nmax - nmin + 1e-8f);

    float4 res;
    float* resp = (float*)&res;
#pragma unroll
    for (int k = 0; k < 4; k++) {
        int xo = xb + k;
        float xin = (xo + 0.5f) * 0.25f - 0.5f;
        int x0 = (int)floorf(xin);
        float fx = xin - (float)x0;
        int x0c = max(x0, 0), x1c = min(x0 + 1, HWF - 1);
        float v = (1.f - fy) * ((1.f - fx) * r0[x0c] + fx * r0[x1c])
                + fy * ((1.f - fx) * r1[x0c] + fx * r1[x1c]);
        resp[k] = (v - nmin) * inv;
    }
    *(float4*)&out[(size_t)b * (OHW * OHW) + yo * OHW + xb] = res;
}

// ---------------------------------------------------------------------------
extern "C" void kernel_launch(void* const* d_in, const int* in_sizes, int n_in,
                              void* d_out, int out_size) {
    (void)in_sizes; (void)n_in; (void)out_size;
    const float* combined = (const float*)d_in[0];
    const float* proj_w   = (const float*)d_in[1];
    const float* proj_b   = (const float*)d_in[2];
    const float* mean     = (const float*)d_in[3];
    const float* inv_cov  = (const float*)d_in[4];
    const float* nmin     = (const float*)d_in[5];
    const float* nmax     = (const float*)d_in[6];
    float* out = (float*)d_out;

    const int prep_total = CC * DPAD + NPOS * DP;
    prep_kernel<<<(prep_total + 255) / 256, 256>>>(proj_w, mean);
    proj_kernel<<<dim3(16, BB), 104>>>(combined, proj_b);
    maha_kernel<<<NPOS, 128>>>(inv_cov);
    upsample_kernel<<<dim3(OHW * OHW / (256 * 4), BB), 256>>>(nmin, nmax, out);
}